// round 2
// baseline (speedup 1.0000x reference)
#include <cuda_runtime.h>
#include <cuda_bf16.h>

#define T_DIM 1024
#define F_DIM 128
#define F4    (F_DIM / 4)      // 32 float4 per t-row
#define UNROLL 8
#define EPS_F 1e-5f

// One warp per (b, c) row. Each thread owns 4 consecutive f-channels (float4),
// keeping 4 running sum/sumsq accumulators. LDG.128/STG.128, fully coalesced
// (32 lanes x 16B = full 512B row per transaction group).
__global__ __launch_bounds__(32, 32)
void cumulative_groupnorm_kernel(const float4* __restrict__ x,
                                 const float* __restrict__ weight,
                                 const float* __restrict__ bias,
                                 float4* __restrict__ out,
                                 int C)
{
    __shared__ float s_inv[T_DIM];   // 1/(t+1) LUT (uniform broadcast reads)
    const int lane = threadIdx.x;
    const int bc   = blockIdx.x;

    #pragma unroll
    for (int i = 0; i < T_DIM / 32; i++)
        s_inv[lane + i * 32] = 1.0f / (float)(lane + i * 32 + 1);
    __syncwarp();

    const int c = bc % C;
    const float w  = weight[c];
    const float bb = bias[c];

    const size_t base = (size_t)bc * T_DIM * F4 + lane;
    const float4* __restrict__ xp = x + base;
    float4* __restrict__ op = out + base;

    float s0 = 0.f, s1 = 0.f, s2 = 0.f, s3 = 0.f;     // running sums
    float q0 = 0.f, q1 = 0.f, q2 = 0.f, q3 = 0.f;     // running sum-of-squares

    #pragma unroll 1
    for (int t = 0; t < T_DIM; t += UNROLL) {
        // Front-batched independent 16B loads -> MLP = UNROLL (128B in flight/thread)
        float4 v[UNROLL];
        #pragma unroll
        for (int j = 0; j < UNROLL; j++)
            v[j] = xp[(size_t)(t + j) * F4];

        #pragma unroll
        for (int j = 0; j < UNROLL; j++) {
            const float4 val = v[j];
            s0 += val.x; s1 += val.y; s2 += val.z; s3 += val.w;
            q0 = fmaf(val.x, val.x, q0);
            q1 = fmaf(val.y, val.y, q1);
            q2 = fmaf(val.z, val.z, q2);
            q3 = fmaf(val.w, val.w, q3);

            const float inv = s_inv[t + j];
            const float m0 = s0 * inv, m1 = s1 * inv, m2 = s2 * inv, m3 = s3 * inv;
            const float r0 = rsqrtf(fmaf(-m0, m0, q0 * inv) + EPS_F);
            const float r1 = rsqrtf(fmaf(-m1, m1, q1 * inv) + EPS_F);
            const float r2 = rsqrtf(fmaf(-m2, m2, q2 * inv) + EPS_F);
            const float r3 = rsqrtf(fmaf(-m3, m3, q3 * inv) + EPS_F);

            float4 o;
            o.x = fmaf((val.x - m0) * r0, w, bb);
            o.y = fmaf((val.y - m1) * r1, w, bb);
            o.z = fmaf((val.z - m2) * r2, w, bb);
            o.w = fmaf((val.w - m3) * r3, w, bb);
            op[(size_t)(t + j) * F4] = o;
        }
    }
}

extern "C" void kernel_launch(void* const* d_in, const int* in_sizes, int n_in,
                              void* d_out, int out_size)
{
    const float4* x     = (const float4*)d_in[0];
    const float* weight = (const float*)d_in[1];
    const float* bias   = (const float*)d_in[2];
    float4* out         = (float4*)d_out;

    const int C    = in_sizes[1];                       // 256
    const int n_bc = in_sizes[0] / (T_DIM * F_DIM);     // B*C = 1024

    cumulative_groupnorm_kernel<<<n_bc, 32>>>(x, weight, bias, out, C);
}

// round 3
// speedup vs baseline: 1.2578x; 1.2578x over previous
#include <cuda_runtime.h>
#include <cuda_bf16.h>

#define T_DIM 1024
#define F_DIM 128
#define UNROLL 8
#define EPS_F 1e-5f

// One block per (b, c) row. 128 threads, thread = f index (coalesced).
// Software-pipelined: tile B's 8 loads are issued before tile A's compute,
// so each warp keeps 8 loads in flight even during compute/store phases.
__global__ __launch_bounds__(128, 8)
void cumulative_groupnorm_kernel(const float* __restrict__ x,
                                 const float* __restrict__ weight,
                                 const float* __restrict__ bias,
                                 float* __restrict__ out,
                                 int C)
{
    __shared__ float s_inv[T_DIM];   // 1/(t+1) LUT (broadcast reads)
    const int f  = threadIdx.x;
    const int bc = blockIdx.x;

    #pragma unroll
    for (int i = 0; i < T_DIM / F_DIM; i++) {
        int idx = f + i * F_DIM;
        s_inv[idx] = 1.0f / (float)(idx + 1);
    }
    __syncthreads();

    const int c = bc % C;
    const float w  = weight[c];
    const float bb = bias[c];

    const size_t base = (size_t)bc * T_DIM * F_DIM + f;
    const float* __restrict__ xp = x + base;
    float* __restrict__ op = out + base;

    float sum = 0.0f, sumsq = 0.0f;

    float vA[UNROLL], vB[UNROLL];

    // Prologue: load tile A (t = 0..7)
    #pragma unroll
    for (int j = 0; j < UNROLL; j++)
        vA[j] = __ldcs(xp + (size_t)j * F_DIM);

    #pragma unroll 1
    for (int t = 0; t < T_DIM; t += 2 * UNROLL) {
        // ---- prefetch tile B (t+8 .. t+15) ----
        #pragma unroll
        for (int j = 0; j < UNROLL; j++)
            vB[j] = __ldcs(xp + (size_t)(t + UNROLL + j) * F_DIM);

        // ---- process + store tile A ----
        #pragma unroll
        for (int j = 0; j < UNROLL; j++) {
            const float val = vA[j];
            sum   += val;
            sumsq  = fmaf(val, val, sumsq);
            const float inv  = s_inv[t + j];
            const float mean = sum * inv;
            const float var  = fmaf(-mean, mean, sumsq * inv);
            const float r    = rsqrtf(var + EPS_F);
            __stcs(op + (size_t)(t + j) * F_DIM, fmaf((val - mean) * r, w, bb));
        }

        // ---- prefetch next tile A (t+16 .. t+23), predicated off past end ----
        if (t + 2 * UNROLL < T_DIM) {
            #pragma unroll
            for (int j = 0; j < UNROLL; j++)
                vA[j] = __ldcs(xp + (size_t)(t + 2 * UNROLL + j) * F_DIM);
        }

        // ---- process + store tile B ----
        #pragma unroll
        for (int j = 0; j < UNROLL; j++) {
            const float val = vB[j];
            sum   += val;
            sumsq  = fmaf(val, val, sumsq);
            const float inv  = s_inv[t + UNROLL + j];
            const float mean = sum * inv;
            const float var  = fmaf(-mean, mean, sumsq * inv);
            const float r    = rsqrtf(var + EPS_F);
            __stcs(op + (size_t)(t + UNROLL + j) * F_DIM, fmaf((val - mean) * r, w, bb));
        }
    }
}

extern "C" void kernel_launch(void* const* d_in, const int* in_sizes, int n_in,
                              void* d_out, int out_size)
{
    const float* x      = (const float*)d_in[0];
    const float* weight = (const float*)d_in[1];
    const float* bias   = (const float*)d_in[2];
    float* out          = (float*)d_out;

    const int C    = in_sizes[1];                       // 256
    const int n_bc = in_sizes[0] / (T_DIM * F_DIM);     // B*C = 1024

    cumulative_groupnorm_kernel<<<n_bc, F_DIM>>>(x, weight, bias, out, C);
}